// round 14
// baseline (speedup 1.0000x reference)
#include <cuda_runtime.h>
#include <cuda_bf16.h>
#include <cstdint>

#define B_   64
#define T_   512
#define IN_  256
#define OUT_ 256
#define H_   512
#define MROWS (B_*T_)
#define OUT_OFF (B_*T_*OUT_)
#define G1_CTAS 84
#define G1_JOBS 2048            // (1024/128) * (MROWS/128)

// u planes are T-MAJOR: row = t*64 + b
__device__ __align__(16) float g_uRe[MROWS*H_];
__device__ __align__(16) float g_uIm[MROWS*H_];
__device__ __align__(16) __nv_bfloat16 g_outsH[MROWS*2*H_];   // b-major (row b*512+t)
__device__ __align__(16) __nv_bfloat16 g_outsL[MROWS*2*H_];
__device__ __align__(16) __nv_bfloat16 g_xH[MROWS*IN_];       // t-major rows
__device__ __align__(16) __nv_bfloat16 g_xL[MROWS*IN_];
__device__ __align__(16) __nv_bfloat16 g_w1H[2*H_*IN_];
__device__ __align__(16) __nv_bfloat16 g_w1L[2*H_*IN_];
__device__ __align__(16) __nv_bfloat16 g_w2H[OUT_*2*H_];
__device__ __align__(16) __nv_bfloat16 g_w2L[OUT_*2*H_];
__device__ int g_mdone[256];    // per-M-tile completion counters (8 N-tiles each)

#define BAR128() asm volatile("bar.sync 1, 128;" ::: "memory")

__device__ __forceinline__ float2 cmul(float2 a, float2 b){return make_float2(a.x*b.x-a.y*b.y, a.x*b.y+a.y*b.x);}
__device__ __forceinline__ float2 cmulc(float2 a, float2 b){return make_float2(a.x*b.x+a.y*b.y, a.y*b.x-a.x*b.y);}
__device__ __forceinline__ float2 mulpi(float2 a){return make_float2(-a.y, a.x);}
__device__ __forceinline__ float2 mulmi(float2 a){return make_float2(a.y, -a.x);}

__device__ __forceinline__ float2 p_add(float2 a, float2 b){
    float2 c;
    asm("{\n\t.reg .b64 ra,rb,rc;\n\t"
        "mov.b64 ra,{%2,%3};\n\tmov.b64 rb,{%4,%5};\n\t"
        "add.rn.f32x2 rc,ra,rb;\n\tmov.b64 {%0,%1},rc;\n\t}"
        : "=f"(c.x), "=f"(c.y)
        : "f"(a.x), "f"(a.y), "f"(b.x), "f"(b.y));
    return c;
}
__device__ __forceinline__ float2 p_fma(float2 a, float2 b, float2 c){
    float2 d;
    asm("{\n\t.reg .b64 ra,rb,rc,rd;\n\t"
        "mov.b64 ra,{%2,%3};\n\tmov.b64 rb,{%4,%5};\n\tmov.b64 rc,{%6,%7};\n\t"
        "fma.rn.f32x2 rd,ra,rb,rc;\n\tmov.b64 {%0,%1},rd;\n\t}"
        : "=f"(d.x), "=f"(d.y)
        : "f"(a.x), "f"(a.y), "f"(b.x), "f"(b.y), "f"(c.x), "f"(c.y));
    return d;
}
#define P_SUB(a, b) p_fma((b), NEG1, (a))

__global__ void reset_kernel()
{
    if (threadIdx.x < 256) g_mdone[threadIdx.x] = 0;
}

// ---------------- fused split: x (transposed to t-major), w1, w2 ----------
#define N4_X  (MROWS*IN_/4)
#define N4_W1 (2*H_*IN_/4)
#define N4_W2 (OUT_*2*H_/4)
__global__ void split_all(const float* __restrict__ x,
                          const float* __restrict__ w1,
                          const float* __restrict__ w2)
{
    int gi = blockIdx.x * blockDim.x + threadIdx.x;
    const float* src; __nv_bfloat16 *hi, *lo; int i, d4;
    if (gi < N4_X) {
        src = x; hi = g_xH; lo = g_xL; i = gi;
        int row = i >> 6, col4 = i & 63;            // 64 float4 per row
        int bb = row >> 9, tt = row & 511;
        d4 = (tt*64 + bb)*64 + col4;                // t-major destination row
    } else if (gi < N4_X + N4_W1) {
        src = w1; hi = g_w1H; lo = g_w1L; i = gi - N4_X; d4 = i;
    } else {
        src = w2; hi = g_w2H; lo = g_w2L; i = gi - N4_X - N4_W1; d4 = i;
    }
    float4 v = ((const float4*)src)[i];
    const float* pv = (const float*)&v;
    #pragma unroll
    for (int j = 0; j < 4; j++) {
        __nv_bfloat16 h = __float2bfloat16(pv[j]);
        hi[4*d4 + j] = h;
        lo[4*d4 + j] = __float2bfloat16(pv[j] - __bfloat162float(h));
    }
}

// ---------------- FFT helpers (champion datapath) ----------------
template<int INV>
__device__ __forceinline__ void dft4p(float2& x0, float2& x1, float2& x2, float2& x3,
                                      float2 NEG1)
{
    float2 t0 = p_add(x0, x2), t2 = P_SUB(x0, x2);
    float2 t1 = p_add(x1, x3), t3 = P_SUB(x1, x3);
    float2 w = INV ? make_float2(-t3.y, t3.x) : make_float2(t3.y, -t3.x);
    x0 = p_add(t0, t1);
    x2 = P_SUB(t0, t1);
    x1 = p_add(t2, w);
    x3 = P_SUB(t2, w);
}

template<int INV>
__device__ __forceinline__ void fft32(float2 y[4], const float2 tw32[5], int lane,
                                      float2 NEG1)
{
    #pragma unroll
    for (int s = 0; s < 5; s++) {
        const int st = 16 >> s;
        const bool hi = (lane & st) != 0;
        const float2 tw = tw32[s];
        const bool odd = (lane & 1) != 0;
        #pragma unroll
        for (int j = 0; j < 4; j++) {
            float2 v = y[j], pv;
            pv.x = __shfl_xor_sync(0xffffffffu, v.x, st);
            pv.y = __shfl_xor_sync(0xffffffffu, v.y, st);
            float2 sum = p_add(v, pv);
            float2 dif = P_SUB(pv, v);
            float2 tv;
            if (s == 4)      tv = dif;
            else if (s == 3) tv = odd ? (INV ? mulpi(dif) : mulmi(dif)) : dif;
            else             tv = INV ? cmulc(dif, tw) : cmul(dif, tw);
            y[j] = hi ? tv : sum;
        }
    }
}

// ---------------- GEMM primitives ----------------
#define MMA16816(d, a, b)                                                     \
    asm volatile("mma.sync.aligned.m16n8k16.row.col.f32.bf16.bf16.f32 "       \
                 "{%0,%1,%2,%3}, {%4,%5,%6,%7}, {%8,%9}, {%0,%1,%2,%3};\n"    \
                 : "+f"(d[0]), "+f"(d[1]), "+f"(d[2]), "+f"(d[3])             \
                 : "r"(a[0]), "r"(a[1]), "r"(a[2]), "r"(a[3]),                \
                   "r"(b[0]), "r"(b[1]))

#define LDMX4(r0, r1, r2, r3, addr)                                           \
    asm volatile("ldmatrix.sync.aligned.m8n8.x4.shared.b16 {%0,%1,%2,%3}, [%4];" \
                 : "=r"(r0), "=r"(r1), "=r"(r2), "=r"(r3) : "r"(addr))

__device__ __forceinline__ void cp16(void* dst, const void* src) {
    uint32_t d = (uint32_t)__cvta_generic_to_shared(dst);
    asm volatile("cp.async.cg.shared.global [%0], [%1], 16;\n" :: "r"(d), "l"(src));
}

#define AS(p, buf, hl, r, c) (p)[((((buf)*2 + (hl))*128 + (r))*40) + (c)]
#define BS(p, buf, hl, r, c) (p)[((((buf)*2 + (hl))*128 + (r))*40) + (c)]
#define GEMM_SMEM ((2*2*128*40 + 2*2*128*40) * 2)   // 81920 bytes
#define FUSED_SMEM (120*1024)                        // forces 1 CTA/SM

// CTA tile 128x128, warp tile 64x32 (2x4 warps), 2-stage pipeline, 256 thr.
// MODE 0: A=g_x* (t-major), W=g_w1*, out -> planes. MODE 1: A=g_outs*, W=g_w2*.
template<int MODE>
__device__ __forceinline__ void gemm_tile(__nv_bfloat16* smem,
                                          int bm0, int bn0,
                                          const float* bias, float* C,
                                          int K, int N)
{
    __nv_bfloat16* Asm = smem;
    __nv_bfloat16* Bsm = smem + 2*2*128*40;

    const __nv_bfloat16* AH = (MODE == 0) ? g_xH : g_outsH;
    const __nv_bfloat16* AL = (MODE == 0) ? g_xL : g_outsL;
    const __nv_bfloat16* WH = (MODE == 0) ? g_w1H : g_w2H;
    const __nv_bfloat16* WL = (MODE == 0) ? g_w1L : g_w2L;

    const int tid = threadIdx.x;
    const int wid = tid >> 5, lane = tid & 31;
    const int wm = wid >> 2, wn = wid & 3;
    const int groupID = lane >> 2, tig = lane & 3;
    const int KT = K / 32;

    const int lr0 = tid >> 2,          lq = (tid & 3) * 8;
    const int lr1 = (tid + 256) >> 2;

    const int a_row = (lane & 15);
    const int a_col = (lane >> 4) * 8;
    const int b_row = ((lane >> 4) << 3) + (lane & 7);
    const int b_col = ((lane >> 3) & 1) * 8;

    float acc[4][4][4];
    #pragma unroll
    for (int mi = 0; mi < 4; mi++)
        #pragma unroll
        for (int ni = 0; ni < 4; ni++)
            #pragma unroll
            for (int j = 0; j < 4; j++) acc[mi][ni][j] = 0.f;

    auto load_tile = [&](int kt, int buf) {
        int k0 = kt * 32;
        cp16(&AS(Asm, buf, 0, lr0, lq), AH + (size_t)(bm0 + lr0)*K + k0 + lq);
        cp16(&AS(Asm, buf, 0, lr1, lq), AH + (size_t)(bm0 + lr1)*K + k0 + lq);
        cp16(&AS(Asm, buf, 1, lr0, lq), AL + (size_t)(bm0 + lr0)*K + k0 + lq);
        cp16(&AS(Asm, buf, 1, lr1, lq), AL + (size_t)(bm0 + lr1)*K + k0 + lq);
        cp16(&BS(Bsm, buf, 0, lr0, lq), WH + (size_t)(bn0 + lr0)*K + k0 + lq);
        cp16(&BS(Bsm, buf, 0, lr1, lq), WH + (size_t)(bn0 + lr1)*K + k0 + lq);
        cp16(&BS(Bsm, buf, 1, lr0, lq), WL + (size_t)(bn0 + lr0)*K + k0 + lq);
        cp16(&BS(Bsm, buf, 1, lr1, lq), WL + (size_t)(bn0 + lr1)*K + k0 + lq);
    };

    load_tile(0, 0);
    asm volatile("cp.async.commit_group;\n");

    for (int kt = 0; kt < KT; kt++) {
        const int buf = kt & 1;
        if (kt + 1 < KT) {
            load_tile(kt + 1, (kt + 1) & 1);
            asm volatile("cp.async.commit_group;\n");
            asm volatile("cp.async.wait_group 1;\n");
        } else {
            asm volatile("cp.async.wait_group 0;\n");
        }
        __syncthreads();

        #pragma unroll
        for (int kk = 0; kk < 2; kk++) {
            const int kb = kk * 16;
            uint32_t aH[4][4], aL[4][4], bH[4][2], bL[4][2];
            #pragma unroll
            for (int mi = 0; mi < 4; mi++) {
                uint32_t adrH = (uint32_t)__cvta_generic_to_shared(
                    &AS(Asm, buf, 0, wm*64 + mi*16 + a_row, kb + a_col));
                uint32_t adrL = (uint32_t)__cvta_generic_to_shared(
                    &AS(Asm, buf, 1, wm*64 + mi*16 + a_row, kb + a_col));
                LDMX4(aH[mi][0], aH[mi][1], aH[mi][2], aH[mi][3], adrH);
                LDMX4(aL[mi][0], aL[mi][1], aL[mi][2], aL[mi][3], adrL);
            }
            #pragma unroll
            for (int nip = 0; nip < 2; nip++) {
                uint32_t adrH = (uint32_t)__cvta_generic_to_shared(
                    &BS(Bsm, buf, 0, wn*32 + nip*16 + b_row, kb + b_col));
                uint32_t adrL = (uint32_t)__cvta_generic_to_shared(
                    &BS(Bsm, buf, 1, wn*32 + nip*16 + b_row, kb + b_col));
                LDMX4(bH[2*nip][0], bH[2*nip][1], bH[2*nip+1][0], bH[2*nip+1][1], adrH);
                LDMX4(bL[2*nip][0], bL[2*nip][1], bL[2*nip+1][0], bL[2*nip+1][1], adrL);
            }
            #pragma unroll
            for (int mi = 0; mi < 4; mi++)
                #pragma unroll
                for (int ni = 0; ni < 4; ni++) {
                    MMA16816(acc[mi][ni], aH[mi], bH[ni]);
                    MMA16816(acc[mi][ni], aH[mi], bL[ni]);
                    MMA16816(acc[mi][ni], aL[mi], bH[ni]);
                }
        }
        __syncthreads();
    }

    #pragma unroll
    for (int mi = 0; mi < 4; mi++) {
        #pragma unroll
        for (int ni = 0; ni < 4; ni++) {
            int r0 = bm0 + wm*64 + mi*16 + groupID;
            int c0 = bn0 + wn*32 + ni*8 + 2*tig;
            float v00 = acc[mi][ni][0], v01 = acc[mi][ni][1];
            float v10 = acc[mi][ni][2], v11 = acc[mi][ni][3];
            if (MODE == 0) {
                float* plane = (c0 < 512) ? g_uRe : g_uIm;
                int cc = (c0 < 512) ? c0 : (c0 - 512);
                plane[(size_t)r0*512 + cc]       = v00;
                plane[(size_t)r0*512 + cc + 1]   = v01;
                plane[(size_t)(r0+8)*512 + cc]   = v10;
                plane[(size_t)(r0+8)*512 + cc+1] = v11;
            } else {
                float b0 = bias[c0], b1 = bias[c0 + 1];
                C[(size_t)r0*N + c0]         = v00 + b0;
                C[(size_t)r0*N + c0 + 1]     = v01 + b1;
                C[(size_t)(r0+8)*N + c0]     = v10 + b0;
                C[(size_t)(r0+8)*N + c0 + 1] = v11 + b1;
            }
        }
    }
}

// standalone GEMM2 (full chip, after fused kernel)
__global__ __launch_bounds__(256)
void gemm2_kernel(const float* __restrict__ bias, float* __restrict__ C)
{
    extern __shared__ __nv_bfloat16 smem[];
    gemm_tile<1>(smem, blockIdx.y * 128, blockIdx.x * 128, bias, C, 2*H_, OUT_);
}

// =========================================================================
// Fused: 64 scan CTAs + 84 persistent GEMM1-producer CTAs; 1 CTA/SM via
// 120KB dynamic smem. Scan waits on g_mdone[m] (m = t>>1) every 16 steps.
// =========================================================================
__global__ __launch_bounds__(256)
void fused_g1_scan(const float* __restrict__ h0,
                   const float* __restrict__ b_h,
                   const float* __restrict__ d1,
                   const float* __restrict__ d2,
                   const float* __restrict__ d3,
                   const float* __restrict__ r1re, const float* __restrict__ r1im,
                   const float* __restrict__ r2re, const float* __restrict__ r2im,
                   const int*   __restrict__ perm,
                   float* __restrict__ dout)
{
    extern __shared__ __nv_bfloat16 dsm[];
    __shared__ float2 SA[544], SB[544];
    __shared__ float2 WE3[544], WE3s[544], V2E3[544], V2E3s[544];
    __shared__ float2 RED1[4], RED2[4];
    __shared__ float  FAC[2];

    // ---------------- GEMM1 producer role ----------------
    if (blockIdx.x >= B_) {
        const int cta = blockIdx.x - B_;
        for (int j = cta; j < G1_JOBS; j += G1_CTAS) {
            int m = j >> 3, nb = j & 7;
            gemm_tile<0>(dsm, m*128, nb*128, nullptr, nullptr, IN_, 1024);
            __syncthreads();
            if (threadIdx.x == 0) {
                __threadfence();
                atomicAdd(&g_mdone[m], 1);
            }
        }
        return;
    }

    // ---------------- scan role ----------------
    if (threadIdx.x >= 128) return;

    const int b    = blockIdx.x;
    const int tid  = threadIdx.x;
    const int lane = tid & 31;
    const int w    = tid >> 5;
    const int R    = __brev(lane) >> 27;
    const float2 NEG1 = make_float2(-1.f, -1.f);

    int oaddr[4];
    #pragma unroll
    for (int j = 0; j < 4; j++) oaddr[j] = R*17 + w + 4*j;

    float2 h[4], e1r[4], e2r[4], e3r[4], v1o[4], v2o[4];
    float bhr[4]; int paddr[4], caddr[4];
    const float inv512 = 1.0f / 512.0f;
    #pragma unroll
    for (int r = 0; r < 4; r++) {
        int idx = tid + 128*r;
        float sn, cs;
        sincosf(d1[idx], &sn, &cs); e1r[r] = make_float2(cs, sn);
        sincosf(d2[idx], &sn, &cs); e2r[r] = make_float2(cs, sn);
        sincosf(d3[idx], &sn, &cs); e3r[r] = make_float2(cs*inv512, sn*inv512);
        bhr[r] = b_h[idx];
        int p = perm[idx];
        paddr[r] = (p >> 4)*17 + (p & 15);
        caddr[r] = (idx >> 4)*17 + (idx & 15);
        h[r] = make_float2(h0[b*1024 + idx], h0[b*1024 + 512 + idx]);
    }
    #pragma unroll
    for (int j = 0; j < 4; j++) {
        int oi = w + 4*j + 16*R;
        v1o[j] = make_float2(r1re[oi], r1im[oi]);
        v2o[j] = make_float2(r2re[oi], r2im[oi]);
    }

    const float TWO_PI = 6.283185307179586f;
    float2 c512[3], d128[3], tw32c[5];
    #pragma unroll
    for (int k = 1; k <= 3; k++) {
        float sn, cs;
        sincosf(-TWO_PI * (float)(tid*k) / 512.0f, &sn, &cs);
        c512[k-1] = make_float2(cs, sn);
        sincosf(-TWO_PI * (float)(lane*k) / 128.0f, &sn, &cs);
        d128[k-1] = make_float2(cs, sn);
    }
    #pragma unroll
    for (int s = 0; s < 5; s++) {
        int st = 16 >> s;
        int e  = (lane & (st - 1)) << s;
        float sn, cs;
        sincosf(-TWO_PI * (float)e / 32.0f, &sn, &cs);
        tw32c[s] = make_float2(cs, sn);
    }

    {   // fac1/fac2
        float n1 = 0.f, n2 = 0.f;
        #pragma unroll
        for (int r = 0; r < 4; r++) {
            int idx = tid + 128*r;
            n1 += r1re[idx]*r1re[idx] + r1im[idx]*r1im[idx];
            n2 += r2re[idx]*r2re[idx] + r2im[idx]*r2im[idx];
        }
        #pragma unroll
        for (int off = 16; off; off >>= 1) {
            n1 += __shfl_xor_sync(0xffffffffu, n1, off);
            n2 += __shfl_xor_sync(0xffffffffu, n2, off);
        }
        if (lane == 0) RED1[w] = make_float2(n1, n2);
        BAR128();
        if (tid == 0) {
            float a  = (RED1[0].x + RED1[1].x) + (RED1[2].x + RED1[3].x);
            float bb = (RED1[0].y + RED1[1].y) + (RED1[2].y + RED1[3].y);
            FAC[0] = 2.f / a; FAC[1] = 2.f / bb;
        }
        BAR128();
    }
    const float fac1 = FAC[0], fac2 = FAC[1];

    float Kx, Ky;
    {
        for (int i = tid; i < 512; i += 128) {
            int a = (i >> 4)*17 + (i & 15);
            SB[a] = make_float2(r1re[i], r1im[i]);
        }
        BAR128();
        float2 yw[4];
        #pragma unroll
        for (int r = 0; r < 4; r++) yw[r] = cmul(SB[paddr[r]], e2r[r]);
        dft4p<1>(yw[0], yw[1], yw[2], yw[3], NEG1);
        yw[1] = cmulc(yw[1], c512[0]);
        yw[2] = cmulc(yw[2], c512[1]);
        yw[3] = cmulc(yw[3], c512[2]);
        #pragma unroll
        for (int r = 0; r < 4; r++) SA[r*128 + tid] = yw[r];
        BAR128();
        #pragma unroll
        for (int q = 0; q < 4; q++) yw[q] = SA[w*128 + 32*q + lane];
        dft4p<1>(yw[0], yw[1], yw[2], yw[3], NEG1);
        yw[1] = cmulc(yw[1], d128[0]);
        yw[2] = cmulc(yw[2], d128[1]);
        yw[3] = cmulc(yw[3], d128[2]);
        fft32<1>(yw, tw32c, lane, NEG1);

        float dx = 0.f, dy = 0.f;
        #pragma unroll
        for (int j = 0; j < 4; j++) {
            dx += yw[j].x*v2o[j].x + yw[j].y*v2o[j].y;
            dy += yw[j].y*v2o[j].x - yw[j].x*v2o[j].y;
        }
        #pragma unroll
        for (int off = 16; off; off >>= 1) {
            dx += __shfl_xor_sync(0xffffffffu, dx, off);
            dy += __shfl_xor_sync(0xffffffffu, dy, off);
        }
        if (lane == 0) RED2[w] = make_float2(dx, dy);
        #pragma unroll
        for (int j = 0; j < 4; j++) SB[oaddr[j]] = yw[j];
        BAR128();
        Kx = ((RED2[0].x + RED2[1].x) + (RED2[2].x + RED2[3].x)) * fac2;
        Ky = ((RED2[0].y + RED2[1].y) + (RED2[2].y + RED2[3].y)) * fac2;
        for (int i = tid; i < 512; i += 128) {
            int a = (i >> 4)*17 + (i & 15);
            float sn, cs; sincosf(d3[i], &sn, &cs);
            float2 e3i = make_float2(cs*inv512, sn*inv512);
            float2 we  = cmul(SB[a], e3i);
            float2 ve  = cmul(make_float2(r2re[i], r2im[i]), e3i);
            WE3[a]   = we;
            WE3s[a]  = make_float2(we.y, -we.x);
            V2E3[a]  = ve;
            V2E3s[a] = make_float2(ve.y, -ve.x);
        }
        BAR128();
    }

    for (int t = 0; t < T_; t++) {
        // wait for u tiles covering t..t+15 (m = row>>7 = t>>1 groups)
        if ((t & 15) == 0) {
            if (tid == 0) {
                int mhi = (t + 15) >> 1;
                for (int m = t >> 1; m <= mhi; m++)
                    while (*(volatile int*)&g_mdone[m] < 8) __nanosleep(100);
                __threadfence();
            }
            BAR128();
        }

        float2 u0[4];
        {
            const size_t urow = (size_t)(t*64 + b) * H_;     // t-major
            const float* upre = g_uRe + urow;
            const float* upim = g_uIm + urow;
            #pragma unroll
            for (int r = 0; r < 4; r++)
                u0[r] = make_float2(upre[tid + 128*r], upim[tid + 128*r]);
        }

        float2 y[4];
        #pragma unroll
        for (int r = 0; r < 4; r++) y[r] = cmul(h[r], e1r[r]);
        dft4p<0>(y[0], y[1], y[2], y[3], NEG1);
        y[1] = cmul(y[1], c512[0]);
        y[2] = cmul(y[2], c512[1]);
        y[3] = cmul(y[3], c512[2]);
        #pragma unroll
        for (int r = 0; r < 4; r++) SA[r*128 + tid] = y[r];
        BAR128();                                             // S1

        #pragma unroll
        for (int q = 0; q < 4; q++) y[q] = SA[w*128 + 32*q + lane];
        dft4p<0>(y[0], y[1], y[2], y[3], NEG1);
        y[1] = cmul(y[1], d128[0]);
        y[2] = cmul(y[2], d128[1]);
        y[3] = cmul(y[3], d128[2]);
        fft32<0>(y, tw32c, lane, NEG1);
        #pragma unroll
        for (int j = 0; j < 4; j++) SB[oaddr[j]] = y[j];
        {
            float dx = 0.f, dy = 0.f;
            #pragma unroll
            for (int j = 0; j < 4; j++) {
                dx += y[j].x*v1o[j].x + y[j].y*v1o[j].y;
                dy += y[j].y*v1o[j].x - y[j].x*v1o[j].y;
            }
            #pragma unroll
            for (int off = 16; off; off >>= 1) {
                dx += __shfl_xor_sync(0xffffffffu, dx, off);
                dy += __shfl_xor_sync(0xffffffffu, dy, off);
            }
            if (lane == 0) RED1[w] = make_float2(dx, dy);
        }
        BAR128();                                             // S2

        #pragma unroll
        for (int r = 0; r < 4; r++) y[r] = cmul(SB[paddr[r]], e2r[r]);
        dft4p<1>(y[0], y[1], y[2], y[3], NEG1);
        y[1] = cmulc(y[1], c512[0]);
        y[2] = cmulc(y[2], c512[1]);
        y[3] = cmulc(y[3], c512[2]);
        #pragma unroll
        for (int r = 0; r < 4; r++) SA[r*128 + tid] = y[r];
        BAR128();                                             // S3

        #pragma unroll
        for (int q = 0; q < 4; q++) y[q] = SA[w*128 + 32*q + lane];
        dft4p<1>(y[0], y[1], y[2], y[3], NEG1);
        y[1] = cmulc(y[1], d128[0]);
        y[2] = cmulc(y[2], d128[1]);
        y[3] = cmulc(y[3], d128[2]);
        fft32<1>(y, tw32c, lane, NEG1);
        #pragma unroll
        for (int j = 0; j < 4; j++) SB[oaddr[j]] = y[j];
        {
            float dx = 0.f, dy = 0.f;
            #pragma unroll
            for (int j = 0; j < 4; j++) {
                dx += y[j].x*v2o[j].x + y[j].y*v2o[j].y;
                dy += y[j].y*v2o[j].x - y[j].x*v2o[j].y;
            }
            #pragma unroll
            for (int off = 16; off; off >>= 1) {
                dx += __shfl_xor_sync(0xffffffffu, dx, off);
                dy += __shfl_xor_sync(0xffffffffu, dy, off);
            }
            if (lane == 0) RED2[w] = make_float2(dx, dy);
        }
        BAR128();                                             // S4

        float2 c1, c2;
        c1.x = ((RED1[0].x + RED1[1].x) + (RED1[2].x + RED1[3].x)) * fac1;
        c1.y = ((RED1[0].y + RED1[1].y) + (RED1[2].y + RED1[3].y)) * fac1;
        float d2x = (RED2[0].x + RED2[1].x) + (RED2[2].x + RED2[3].x);
        float d2y = (RED2[0].y + RED2[1].y) + (RED2[2].y + RED2[3].y);
        c2.x = fac2*d2x - (c1.x*Kx - c1.y*Ky);
        c2.y = fac2*d2y - (c1.x*Ky + c1.y*Kx);

        const float2 c1nx = make_float2(-c1.x, -c1.x), c1y = make_float2(c1.y, c1.y);
        const float2 c2nx = make_float2(-c2.x, -c2.x), c2y = make_float2(c2.y, c2.y);

        const int orow = (b*T_ + t) * (2*H_);                 // outs stays b-major
        #pragma unroll
        for (int r = 0; r < 4; r++) {
            int a = caddr[r];
            float2 y0c = SB[a];
            float2 s = cmul(y0c, e3r[r]);
            s = p_fma(c1y,  WE3s[a], s);
            s = p_fma(c1nx, WE3[a],  s);
            s = p_fma(c2y,  V2E3s[a], s);
            s = p_fma(c2nx, V2E3[a],  s);
            float2 pre = p_add(u0[r], s);
            float n2v = pre.x*pre.x + pre.y*pre.y;
            float rn  = rsqrtf(fmaxf(n2v, 1e-18f));
            float norm = n2v * rn;
            float sc = fmaxf(norm + bhr[r], 0.f) * __fdividef(1.f, norm + 1e-6f);
            float2 nw = make_float2(pre.x*sc, pre.y*sc);
            h[r] = nw;
            int idx = tid + 128*r;
            __nv_bfloat16 hx = __float2bfloat16(nw.x);
            __nv_bfloat16 hy = __float2bfloat16(nw.y);
            g_outsH[orow + idx]       = hx;
            g_outsL[orow + idx]       = __float2bfloat16(nw.x - __bfloat162float(hx));
            g_outsH[orow + 512 + idx] = hy;
            g_outsL[orow + 512 + idx] = __float2bfloat16(nw.y - __bfloat162float(hy));
        }
    }

    #pragma unroll
    for (int r = 0; r < 4; r++) {
        int idx = tid + 128*r;
        dout[OUT_OFF + b*1024 + idx]       = h[r].x;
        dout[OUT_OFF + b*1024 + 512 + idx] = h[r].y;
    }
}

// =========================================================================
extern "C" void kernel_launch(void* const* d_in, const int* in_sizes, int n_in,
                              void* d_out, int out_size)
{
    const float* x    = (const float*)d_in[0];
    const float* h0   = (const float*)d_in[1];
    const float* itoh = (const float*)d_in[2];
    const float* fcw  = (const float*)d_in[3];
    const float* fcb  = (const float*)d_in[4];
    const float* bh   = (const float*)d_in[5];
    const float* d1   = (const float*)d_in[6];
    const float* d2   = (const float*)d_in[7];
    const float* d3   = (const float*)d_in[8];
    const float* r1re = (const float*)d_in[9];
    const float* r1im = (const float*)d_in[10];
    const float* r2re = (const float*)d_in[11];
    const float* r2im = (const float*)d_in[12];
    const int*   perm = (const int*)d_in[13];
    float* out = (float*)d_out;

    cudaFuncSetAttribute(fused_g1_scan, cudaFuncAttributeMaxDynamicSharedMemorySize, FUSED_SMEM);
    cudaFuncSetAttribute(gemm2_kernel,  cudaFuncAttributeMaxDynamicSharedMemorySize, GEMM_SMEM);

    reset_kernel<<<1, 256>>>();
    split_all<<<(N4_X + N4_W1 + N4_W2 + 255)/256, 256>>>(x, itoh, fcw);

    // fused: 64 scan CTAs + 84 GEMM1 producers, 1 CTA/SM
    fused_g1_scan<<<B_ + G1_CTAS, 256, FUSED_SMEM>>>(
        h0, bh, d1, d2, d3, r1re, r1im, r2re, r2im, perm, out);

    // GEMM2 at full chip width
    gemm2_kernel<<<dim3(256/128, MROWS/128), 256, GEMM_SMEM>>>(fcb, out);
}

// round 15
// speedup vs baseline: 1.2705x; 1.2705x over previous
#include <cuda_runtime.h>
#include <cuda_bf16.h>
#include <cstdint>

#define B_   64
#define T_   512
#define IN_  256
#define OUT_ 256
#define H_   512
#define MROWS (B_*T_)
#define OUT_OFF (B_*T_*OUT_)

__device__ __align__(16) float g_uRe[MROWS*H_];
__device__ __align__(16) float g_uIm[MROWS*H_];
__device__ __align__(16) __nv_bfloat16 g_outsH[MROWS*2*H_];
__device__ __align__(16) __nv_bfloat16 g_outsL[MROWS*2*H_];
__device__ __align__(16) __nv_bfloat16 g_xH[MROWS*IN_];
__device__ __align__(16) __nv_bfloat16 g_xL[MROWS*IN_];
__device__ __align__(16) __nv_bfloat16 g_w1H[2*H_*IN_];
__device__ __align__(16) __nv_bfloat16 g_w1L[2*H_*IN_];
__device__ __align__(16) __nv_bfloat16 g_w2H[OUT_*2*H_];
__device__ __align__(16) __nv_bfloat16 g_w2L[OUT_*2*H_];

__device__ __forceinline__ float2 cmul(float2 a, float2 b){return make_float2(a.x*b.x-a.y*b.y, a.x*b.y+a.y*b.x);}
__device__ __forceinline__ float2 cmulc(float2 a, float2 b){return make_float2(a.x*b.x+a.y*b.y, a.y*b.x-a.x*b.y);}
__device__ __forceinline__ float2 mulpi(float2 a){return make_float2(-a.y, a.x);}
__device__ __forceinline__ float2 mulmi(float2 a){return make_float2(a.y, -a.x);}

// ---------------- packed f32x2 helpers ----------------
__device__ __forceinline__ float2 p_add(float2 a, float2 b){
    float2 c;
    asm("{\n\t.reg .b64 ra,rb,rc;\n\t"
        "mov.b64 ra,{%2,%3};\n\tmov.b64 rb,{%4,%5};\n\t"
        "add.rn.f32x2 rc,ra,rb;\n\tmov.b64 {%0,%1},rc;\n\t}"
        : "=f"(c.x), "=f"(c.y)
        : "f"(a.x), "f"(a.y), "f"(b.x), "f"(b.y));
    return c;
}
__device__ __forceinline__ float2 p_fma(float2 a, float2 b, float2 c){
    float2 d;
    asm("{\n\t.reg .b64 ra,rb,rc,rd;\n\t"
        "mov.b64 ra,{%2,%3};\n\tmov.b64 rb,{%4,%5};\n\tmov.b64 rc,{%6,%7};\n\t"
        "fma.rn.f32x2 rd,ra,rb,rc;\n\tmov.b64 {%0,%1},rd;\n\t}"
        : "=f"(d.x), "=f"(d.y)
        : "f"(a.x), "f"(a.y), "f"(b.x), "f"(b.y), "f"(c.x), "f"(c.y));
    return d;
}
#define P_SUB(a, b) p_fma((b), NEG1, (a))

// ---------------- fused split kernel ----------------
#define N4_X  (MROWS*IN_/4)
#define N4_W1 (2*H_*IN_/4)
#define N4_W2 (OUT_*2*H_/4)
__global__ void split_all(const float* __restrict__ x,
                          const float* __restrict__ w1,
                          const float* __restrict__ w2)
{
    int gi = blockIdx.x * blockDim.x + threadIdx.x;
    const float* src; __nv_bfloat16 *hi, *lo; int i;
    if (gi < N4_X)                 { src = x;  hi = g_xH;  lo = g_xL;  i = gi; }
    else if (gi < N4_X + N4_W1)    { src = w1; hi = g_w1H; lo = g_w1L; i = gi - N4_X; }
    else                            { src = w2; hi = g_w2H; lo = g_w2L; i = gi - N4_X - N4_W1; }
    float4 v = ((const float4*)src)[i];
    const float* pv = (const float*)&v;
    #pragma unroll
    for (int j = 0; j < 4; j++) {
        __nv_bfloat16 h = __float2bfloat16(pv[j]);
        hi[4*i + j] = h;
        lo[4*i + j] = __float2bfloat16(pv[j] - __bfloat162float(h));
    }
}

template<int INV>
__device__ __forceinline__ void dft4p(float2& x0, float2& x1, float2& x2, float2& x3,
                                      float2 NEG1)
{
    float2 t0 = p_add(x0, x2), t2 = P_SUB(x0, x2);
    float2 t1 = p_add(x1, x3), t3 = P_SUB(x1, x3);
    float2 w = INV ? make_float2(-t3.y, t3.x) : make_float2(t3.y, -t3.x);
    x0 = p_add(t0, t1);
    x2 = P_SUB(t0, t1);
    x1 = p_add(t2, w);
    x3 = P_SUB(t2, w);
}

template<int INV>
__device__ __forceinline__ void fft32(float2 y[4], const float2 tw32[5], int lane,
                                      float2 NEG1)
{
    #pragma unroll
    for (int s = 0; s < 5; s++) {
        const int st = 16 >> s;
        const bool hi = (lane & st) != 0;
        const float2 tw = tw32[s];
        const bool odd = (lane & 1) != 0;
        #pragma unroll
        for (int j = 0; j < 4; j++) {
            float2 v = y[j], pv;
            pv.x = __shfl_xor_sync(0xffffffffu, v.x, st);
            pv.y = __shfl_xor_sync(0xffffffffu, v.y, st);
            float2 sum = p_add(v, pv);
            float2 dif = P_SUB(pv, v);
            float2 tv;
            if (s == 4)      tv = dif;
            else if (s == 3) tv = odd ? (INV ? mulpi(dif) : mulmi(dif)) : dif;
            else             tv = INV ? cmulc(dif, tw) : cmul(dif, tw);
            y[j] = hi ? tv : sum;
        }
    }
}

// =========================================================================
// Scan: 1 chain/CTA, 128 thr (champion datapath, unchanged)
// =========================================================================
__global__ __launch_bounds__(128)
void scan_kernel(const float* __restrict__ h0,
                 const float* __restrict__ b_h,
                 const float* __restrict__ d1,
                 const float* __restrict__ d2,
                 const float* __restrict__ d3,
                 const float* __restrict__ r1re, const float* __restrict__ r1im,
                 const float* __restrict__ r2re, const float* __restrict__ r2im,
                 const int*   __restrict__ perm,
                 float* __restrict__ dout)
{
    __shared__ float2 SA[544], SB[544];
    __shared__ float2 WE3[544], WE3s[544], V2E3[544], V2E3s[544];
    __shared__ float2 RED1[4], RED2[4];
    __shared__ float  FAC[2];

    const int b    = blockIdx.x;
    const int tid  = threadIdx.x;
    const int lane = tid & 31;
    const int w    = tid >> 5;
    const int R    = __brev(lane) >> 27;
    const float2 NEG1 = make_float2(-1.f, -1.f);

    int oaddr[4];
    #pragma unroll
    for (int j = 0; j < 4; j++) oaddr[j] = R*17 + w + 4*j;

    float2 h[4], e1r[4], e2r[4], e3r[4], v1o[4], v2o[4];
    float bhr[4]; int paddr[4], caddr[4];
    const float inv512 = 1.0f / 512.0f;
    #pragma unroll
    for (int r = 0; r < 4; r++) {
        int idx = tid + 128*r;
        float sn, cs;
        sincosf(d1[idx], &sn, &cs); e1r[r] = make_float2(cs, sn);
        sincosf(d2[idx], &sn, &cs); e2r[r] = make_float2(cs, sn);
        sincosf(d3[idx], &sn, &cs); e3r[r] = make_float2(cs*inv512, sn*inv512);
        bhr[r] = b_h[idx];
        int p = perm[idx];
        paddr[r] = (p >> 4)*17 + (p & 15);
        caddr[r] = (idx >> 4)*17 + (idx & 15);
        h[r] = make_float2(h0[b*1024 + idx], h0[b*1024 + 512 + idx]);
    }
    #pragma unroll
    for (int j = 0; j < 4; j++) {
        int oi = w + 4*j + 16*R;
        v1o[j] = make_float2(r1re[oi], r1im[oi]);
        v2o[j] = make_float2(r2re[oi], r2im[oi]);
    }

    const float TWO_PI = 6.283185307179586f;
    float2 c512[3], d128[3], tw32c[5];
    #pragma unroll
    for (int k = 1; k <= 3; k++) {
        float sn, cs;
        sincosf(-TWO_PI * (float)(tid*k) / 512.0f, &sn, &cs);
        c512[k-1] = make_float2(cs, sn);
        sincosf(-TWO_PI * (float)(lane*k) / 128.0f, &sn, &cs);
        d128[k-1] = make_float2(cs, sn);
    }
    #pragma unroll
    for (int s = 0; s < 5; s++) {
        int st = 16 >> s;
        int e  = (lane & (st - 1)) << s;
        float sn, cs;
        sincosf(-TWO_PI * (float)e / 32.0f, &sn, &cs);
        tw32c[s] = make_float2(cs, sn);
    }

    {   // fac1/fac2
        float n1 = 0.f, n2 = 0.f;
        #pragma unroll
        for (int r = 0; r < 4; r++) {
            int idx = tid + 128*r;
            n1 += r1re[idx]*r1re[idx] + r1im[idx]*r1im[idx];
            n2 += r2re[idx]*r2re[idx] + r2im[idx]*r2im[idx];
        }
        #pragma unroll
        for (int off = 16; off; off >>= 1) {
            n1 += __shfl_xor_sync(0xffffffffu, n1, off);
            n2 += __shfl_xor_sync(0xffffffffu, n2, off);
        }
        if (lane == 0) RED1[w] = make_float2(n1, n2);
        __syncthreads();
        if (tid == 0) {
            float a  = (RED1[0].x + RED1[1].x) + (RED1[2].x + RED1[3].x);
            float bb = (RED1[0].y + RED1[1].y) + (RED1[2].y + RED1[3].y);
            FAC[0] = 2.f / a; FAC[1] = 2.f / bb;
        }
        __syncthreads();
    }
    const float fac1 = FAC[0], fac2 = FAC[1];

    float Kx, Ky;
    {
        for (int i = tid; i < 512; i += 128) {
            int a = (i >> 4)*17 + (i & 15);
            SB[a] = make_float2(r1re[i], r1im[i]);
        }
        __syncthreads();
        float2 yw[4];
        #pragma unroll
        for (int r = 0; r < 4; r++) yw[r] = cmul(SB[paddr[r]], e2r[r]);
        dft4p<1>(yw[0], yw[1], yw[2], yw[3], NEG1);
        yw[1] = cmulc(yw[1], c512[0]);
        yw[2] = cmulc(yw[2], c512[1]);
        yw[3] = cmulc(yw[3], c512[2]);
        #pragma unroll
        for (int r = 0; r < 4; r++) SA[r*128 + tid] = yw[r];
        __syncthreads();
        #pragma unroll
        for (int q = 0; q < 4; q++) yw[q] = SA[w*128 + 32*q + lane];
        dft4p<1>(yw[0], yw[1], yw[2], yw[3], NEG1);
        yw[1] = cmulc(yw[1], d128[0]);
        yw[2] = cmulc(yw[2], d128[1]);
        yw[3] = cmulc(yw[3], d128[2]);
        fft32<1>(yw, tw32c, lane, NEG1);

        float dx = 0.f, dy = 0.f;
        #pragma unroll
        for (int j = 0; j < 4; j++) {
            dx += yw[j].x*v2o[j].x + yw[j].y*v2o[j].y;
            dy += yw[j].y*v2o[j].x - yw[j].x*v2o[j].y;
        }
        #pragma unroll
        for (int off = 16; off; off >>= 1) {
            dx += __shfl_xor_sync(0xffffffffu, dx, off);
            dy += __shfl_xor_sync(0xffffffffu, dy, off);
        }
        if (lane == 0) RED2[w] = make_float2(dx, dy);
        #pragma unroll
        for (int j = 0; j < 4; j++) SB[oaddr[j]] = yw[j];
        __syncthreads();
        Kx = ((RED2[0].x + RED2[1].x) + (RED2[2].x + RED2[3].x)) * fac2;
        Ky = ((RED2[0].y + RED2[1].y) + (RED2[2].y + RED2[3].y)) * fac2;
        for (int i = tid; i < 512; i += 128) {
            int a = (i >> 4)*17 + (i & 15);
            float sn, cs; sincosf(d3[i], &sn, &cs);
            float2 e3i = make_float2(cs*inv512, sn*inv512);
            float2 we  = cmul(SB[a], e3i);
            float2 ve  = cmul(make_float2(r2re[i], r2im[i]), e3i);
            WE3[a]   = we;
            WE3s[a]  = make_float2(we.y, -we.x);
            V2E3[a]  = ve;
            V2E3s[a] = make_float2(ve.y, -ve.x);
        }
        __syncthreads();
    }

    const int brow = b * T_;

    for (int t = 0; t < T_; t++) {
        float2 u0[4];
        {
            const float* upre = g_uRe + (size_t)(brow + t) * H_;
            const float* upim = g_uIm + (size_t)(brow + t) * H_;
            #pragma unroll
            for (int r = 0; r < 4; r++)
                u0[r] = make_float2(upre[tid + 128*r], upim[tid + 128*r]);
        }

        float2 y[4];
        #pragma unroll
        for (int r = 0; r < 4; r++) y[r] = cmul(h[r], e1r[r]);
        dft4p<0>(y[0], y[1], y[2], y[3], NEG1);
        y[1] = cmul(y[1], c512[0]);
        y[2] = cmul(y[2], c512[1]);
        y[3] = cmul(y[3], c512[2]);
        #pragma unroll
        for (int r = 0; r < 4; r++) SA[r*128 + tid] = y[r];
        __syncthreads();                                              // S1

        #pragma unroll
        for (int q = 0; q < 4; q++) y[q] = SA[w*128 + 32*q + lane];
        dft4p<0>(y[0], y[1], y[2], y[3], NEG1);
        y[1] = cmul(y[1], d128[0]);
        y[2] = cmul(y[2], d128[1]);
        y[3] = cmul(y[3], d128[2]);
        fft32<0>(y, tw32c, lane, NEG1);
        #pragma unroll
        for (int j = 0; j < 4; j++) SB[oaddr[j]] = y[j];
        {
            float dx = 0.f, dy = 0.f;
            #pragma unroll
            for (int j = 0; j < 4; j++) {
                dx += y[j].x*v1o[j].x + y[j].y*v1o[j].y;
                dy += y[j].y*v1o[j].x - y[j].x*v1o[j].y;
            }
            #pragma unroll
            for (int off = 16; off; off >>= 1) {
                dx += __shfl_xor_sync(0xffffffffu, dx, off);
                dy += __shfl_xor_sync(0xffffffffu, dy, off);
            }
            if (lane == 0) RED1[w] = make_float2(dx, dy);
        }
        __syncthreads();                                              // S2

        #pragma unroll
        for (int r = 0; r < 4; r++) y[r] = cmul(SB[paddr[r]], e2r[r]);
        dft4p<1>(y[0], y[1], y[2], y[3], NEG1);
        y[1] = cmulc(y[1], c512[0]);
        y[2] = cmulc(y[2], c512[1]);
        y[3] = cmulc(y[3], c512[2]);
        #pragma unroll
        for (int r = 0; r < 4; r++) SA[r*128 + tid] = y[r];
        __syncthreads();                                              // S3

        #pragma unroll
        for (int q = 0; q < 4; q++) y[q] = SA[w*128 + 32*q + lane];
        dft4p<1>(y[0], y[1], y[2], y[3], NEG1);
        y[1] = cmulc(y[1], d128[0]);
        y[2] = cmulc(y[2], d128[1]);
        y[3] = cmulc(y[3], d128[2]);
        fft32<1>(y, tw32c, lane, NEG1);
        #pragma unroll
        for (int j = 0; j < 4; j++) SB[oaddr[j]] = y[j];
        {
            float dx = 0.f, dy = 0.f;
            #pragma unroll
            for (int j = 0; j < 4; j++) {
                dx += y[j].x*v2o[j].x + y[j].y*v2o[j].y;
                dy += y[j].y*v2o[j].x - y[j].x*v2o[j].y;
            }
            #pragma unroll
            for (int off = 16; off; off >>= 1) {
                dx += __shfl_xor_sync(0xffffffffu, dx, off);
                dy += __shfl_xor_sync(0xffffffffu, dy, off);
            }
            if (lane == 0) RED2[w] = make_float2(dx, dy);
        }
        __syncthreads();                                              // S4

        float2 c1, c2;
        c1.x = ((RED1[0].x + RED1[1].x) + (RED1[2].x + RED1[3].x)) * fac1;
        c1.y = ((RED1[0].y + RED1[1].y) + (RED1[2].y + RED1[3].y)) * fac1;
        float d2x = (RED2[0].x + RED2[1].x) + (RED2[2].x + RED2[3].x);
        float d2y = (RED2[0].y + RED2[1].y) + (RED2[2].y + RED2[3].y);
        c2.x = fac2*d2x - (c1.x*Kx - c1.y*Ky);
        c2.y = fac2*d2y - (c1.x*Ky + c1.y*Kx);

        const float2 c1nx = make_float2(-c1.x, -c1.x), c1y = make_float2(c1.y, c1.y);
        const float2 c2nx = make_float2(-c2.x, -c2.x), c2y = make_float2(c2.y, c2.y);

        const int orow = (brow + t) * (2*H_);
        #pragma unroll
        for (int r = 0; r < 4; r++) {
            int a = caddr[r];
            float2 y0c = SB[a];
            float2 s = cmul(y0c, e3r[r]);
            s = p_fma(c1y,  WE3s[a], s);
            s = p_fma(c1nx, WE3[a],  s);
            s = p_fma(c2y,  V2E3s[a], s);
            s = p_fma(c2nx, V2E3[a],  s);
            float2 pre = p_add(u0[r], s);
            float n2v = pre.x*pre.x + pre.y*pre.y;
            float rn  = rsqrtf(fmaxf(n2v, 1e-18f));
            float norm = n2v * rn;
            float sc = fmaxf(norm + bhr[r], 0.f) * __fdividef(1.f, norm + 1e-6f);
            float2 nw = make_float2(pre.x*sc, pre.y*sc);
            h[r] = nw;
            int idx = tid + 128*r;
            __nv_bfloat16 hx = __float2bfloat16(nw.x);
            __nv_bfloat16 hy = __float2bfloat16(nw.y);
            g_outsH[orow + idx]       = hx;
            g_outsL[orow + idx]       = __float2bfloat16(nw.x - __bfloat162float(hx));
            g_outsH[orow + 512 + idx] = hy;
            g_outsL[orow + 512 + idx] = __float2bfloat16(nw.y - __bfloat162float(hy));
        }
    }

    #pragma unroll
    for (int r = 0; r < 4; r++) {
        int idx = tid + 128*r;
        dout[OUT_OFF + b*1024 + idx]       = h[r].x;
        dout[OUT_OFF + b*1024 + 512 + idx] = h[r].y;
    }
}

// =========================================================================
// bf16x3 GEMM: CTA tile 128x128, warp tile 64x32 (2x4 warps), 2 buffers,
// ONE __syncthreads per k-iter (prefetch issued AFTER the barrier; the
// barrier both frees buffer (kt+1)&1 and publishes buffer kt&1).
// =========================================================================
#define MMA16816(d, a, b)                                                     \
    asm volatile("mma.sync.aligned.m16n8k16.row.col.f32.bf16.bf16.f32 "       \
                 "{%0,%1,%2,%3}, {%4,%5,%6,%7}, {%8,%9}, {%0,%1,%2,%3};\n"    \
                 : "+f"(d[0]), "+f"(d[1]), "+f"(d[2]), "+f"(d[3])             \
                 : "r"(a[0]), "r"(a[1]), "r"(a[2]), "r"(a[3]),                \
                   "r"(b[0]), "r"(b[1]))

#define LDMX4(r0, r1, r2, r3, addr)                                           \
    asm volatile("ldmatrix.sync.aligned.m8n8.x4.shared.b16 {%0,%1,%2,%3}, [%4];" \
                 : "=r"(r0), "=r"(r1), "=r"(r2), "=r"(r3) : "r"(addr))

__device__ __forceinline__ void cp16(void* dst, const void* src) {
    uint32_t d = (uint32_t)__cvta_generic_to_shared(dst);
    asm volatile("cp.async.cg.shared.global [%0], [%1], 16;\n" :: "r"(d), "l"(src));
}

#define AS(p, buf, hl, r, c) (p)[((((buf)*2 + (hl))*128 + (r))*40) + (c)]
#define BS(p, buf, hl, r, c) (p)[((((buf)*2 + (hl))*128 + (r))*40) + (c)]
#define GEMM_SMEM ((2*2*128*40 + 2*2*128*40) * 2)   // 81920 bytes, 2 CTAs/SM

template<int MODE>
__global__ __launch_bounds__(256)
void gemm_bf16s(const float* __restrict__ bias,
                float* __restrict__ C, int M, int N, int K)
{
    extern __shared__ __nv_bfloat16 smem[];
    __nv_bfloat16* Asm = smem;
    __nv_bfloat16* Bsm = smem + 2*2*128*40;

    const __nv_bfloat16* AH = (MODE == 0) ? g_xH : g_outsH;
    const __nv_bfloat16* AL = (MODE == 0) ? g_xL : g_outsL;
    const __nv_bfloat16* WH = (MODE == 0) ? g_w1H : g_w2H;
    const __nv_bfloat16* WL = (MODE == 0) ? g_w1L : g_w2L;

    const int tid = threadIdx.x;
    const int wid = tid >> 5, lane = tid & 31;
    const int wm = wid >> 2, wn = wid & 3;
    const int groupID = lane >> 2, tig = lane & 3;
    const int bm0 = blockIdx.y * 128;
    const int bn0 = blockIdx.x * 128;
    const int KT = K / 32;

    const int lr0 = tid >> 2,          lq = (tid & 3) * 8;
    const int lr1 = (tid + 256) >> 2;

    const int a_row = (lane & 15);
    const int a_col = (lane >> 4) * 8;
    const int b_row = ((lane >> 4) << 3) + (lane & 7);
    const int b_col = ((lane >> 3) & 1) * 8;

    float acc[4][4][4];
    #pragma unroll
    for (int mi = 0; mi < 4; mi++)
        #pragma unroll
        for (int ni = 0; ni < 4; ni++)
            #pragma unroll
            for (int j = 0; j < 4; j++) acc[mi][ni][j] = 0.f;

    auto load_tile = [&](int kt, int buf) {
        int k0 = kt * 32;
        cp16(&AS(Asm, buf, 0, lr0, lq), AH + (size_t)(bm0 + lr0)*K + k0 + lq);
        cp16(&AS(Asm, buf, 0, lr1, lq), AH + (size_t)(bm0 + lr1)*K + k0 + lq);
        cp16(&AS(Asm, buf, 1, lr0, lq), AL + (size_t)(bm0 + lr0)*K + k0 + lq);
        cp16(&AS(Asm, buf, 1, lr1, lq), AL + (size_t)(bm0 + lr1)*K + k0 + lq);
        cp16(&BS(Bsm, buf, 0, lr0, lq), WH + (size_t)(bn0 + lr0)*K + k0 + lq);
        cp16(&BS(Bsm, buf, 0, lr1, lq), WH + (size_t)(bn0 + lr1)*K + k0 + lq);
        cp16(&BS(Bsm, buf, 1, lr0, lq), WL + (size_t)(bn0 + lr0)*K + k0 + lq);
        cp16(&BS(Bsm, buf, 1, lr1, lq), WL + (size_t)(bn0 + lr1)*K + k0 + lq);
    };

    load_tile(0, 0);
    asm volatile("cp.async.commit_group;\n");

    for (int kt = 0; kt < KT; kt++) {
        const int buf = kt & 1;
        // all committed groups (latest = group kt) must be done
        asm volatile("cp.async.wait_group 0;\n");
        __syncthreads();   // publishes buf kt, and frees buf kt^1 (prev readers done)

        if (kt + 1 < KT) {
            load_tile(kt + 1, buf ^ 1);
            asm volatile("cp.async.commit_group;\n");
        }

        #pragma unroll
        for (int kk = 0; kk < 2; kk++) {
            const int kb = kk * 16;
            uint32_t aH[4][4], aL[4][4], bH[4][2], bL[4][2];
            #pragma unroll
            for (int mi = 0; mi < 4; mi++) {
                uint32_t adrH = (uint32_t)__cvta_generic_to_shared(
                    &AS(Asm, buf, 0, wm*64 + mi*16 + a_row, kb + a_col));
                uint32_t adrL = (uint32_t)__cvta_generic_to_shared(
                    &AS(Asm, buf, 1, wm*64 + mi*16 + a_row, kb + a_col));
                LDMX4(aH[mi][0], aH[mi][1], aH[mi][2], aH[mi][3], adrH);
                LDMX4(aL[mi][0], aL[mi][1], aL[mi][2], aL[mi][3], adrL);
            }
            #pragma unroll
            for (int nip = 0; nip < 2; nip++) {
                uint32_t adrH = (uint32_t)__cvta_generic_to_shared(
                    &BS(Bsm, buf, 0, wn*32 + nip*16 + b_row, kb + b_col));
                uint32_t adrL = (uint32_t)__cvta_generic_to_shared(
                    &BS(Bsm, buf, 1, wn*32 + nip*16 + b_row, kb + b_col));
                LDMX4(bH[2*nip][0], bH[2*nip][1], bH[2*nip+1][0], bH[2*nip+1][1], adrH);
                LDMX4(bL[2*nip][0], bL[2*nip][1], bL[2*nip+1][0], bL[2*nip+1][1], adrL);
            }
            #pragma unroll
            for (int mi = 0; mi < 4; mi++)
                #pragma unroll
                for (int ni = 0; ni < 4; ni++) {
                    MMA16816(acc[mi][ni], aH[mi], bH[ni]);
                    MMA16816(acc[mi][ni], aH[mi], bL[ni]);
                    MMA16816(acc[mi][ni], aL[mi], bH[ni]);
                }
        }
        // no trailing barrier: next iteration's barrier (after wait_group)
        // orders this iteration's smem reads before the next overwrite.
    }

    #pragma unroll
    for (int mi = 0; mi < 4; mi++) {
        #pragma unroll
        for (int ni = 0; ni < 4; ni++) {
            int r0 = bm0 + wm*64 + mi*16 + groupID;
            int c0 = bn0 + wn*32 + ni*8 + 2*tig;
            float v00 = acc[mi][ni][0], v01 = acc[mi][ni][1];
            float v10 = acc[mi][ni][2], v11 = acc[mi][ni][3];
            if (MODE == 0) {
                float* plane = (c0 < 512) ? g_uRe : g_uIm;
                int cc = (c0 < 512) ? c0 : (c0 - 512);
                plane[(size_t)r0*512 + cc]       = v00;
                plane[(size_t)r0*512 + cc + 1]   = v01;
                plane[(size_t)(r0+8)*512 + cc]   = v10;
                plane[(size_t)(r0+8)*512 + cc+1] = v11;
            } else {
                float b0 = bias[c0], b1 = bias[c0 + 1];
                C[(size_t)r0*N + c0]         = v00 + b0;
                C[(size_t)r0*N + c0 + 1]     = v01 + b1;
                C[(size_t)(r0+8)*N + c0]     = v10 + b0;
                C[(size_t)(r0+8)*N + c0 + 1] = v11 + b1;
            }
        }
    }
}

extern "C" void kernel_launch(void* const* d_in, const int* in_sizes, int n_in,
                              void* d_out, int out_size)
{
    const float* x    = (const float*)d_in[0];
    const float* h0   = (const float*)d_in[1];
    const float* itoh = (const float*)d_in[2];
    const float* fcw  = (const float*)d_in[3];
    const float* fcb  = (const float*)d_in[4];
    const float* bh   = (const float*)d_in[5];
    const float* d1   = (const float*)d_in[6];
    const float* d2   = (const float*)d_in[7];
    const float* d3   = (const float*)d_in[8];
    const float* r1re = (const float*)d_in[9];
    const float* r1im = (const float*)d_in[10];
    const float* r2re = (const float*)d_in[11];
    const float* r2im = (const float*)d_in[12];
    const int*   perm = (const int*)d_in[13];
    float* out = (float*)d_out;

    cudaFuncSetAttribute(gemm_bf16s<0>, cudaFuncAttributeMaxDynamicSharedMemorySize, GEMM_SMEM);
    cudaFuncSetAttribute(gemm_bf16s<1>, cudaFuncAttributeMaxDynamicSharedMemorySize, GEMM_SMEM);

    split_all<<<(N4_X + N4_W1 + N4_W2 + 255)/256, 256>>>(x, itoh, fcw);

    // GEMM1: u = x @ itoh^T -> g_uRe/g_uIm  (M=32768, N=1024, K=256)
    gemm_bf16s<0><<<dim3(1024/128, MROWS/128), 256, GEMM_SMEM>>>(nullptr, nullptr,
                                                                 MROWS, 1024, 256);
    // scan
    scan_kernel<<<B_, 128>>>(h0, bh, d1, d2, d3, r1re, r1im, r2re, r2im, perm, out);
    // GEMM2: outputs = outs @ fc_w^T + fc_b  (M=32768, N=256, K=1024)
    gemm_bf16s<1><<<dim3(256/128, MROWS/128), 256, GEMM_SMEM>>>(fcb, out,
                                                                MROWS, 256, 1024);
}